// round 5
// baseline (speedup 1.0000x reference)
#include <cuda_runtime.h>
#include <cstdint>

// ESN: s_t = tanh(U_t + W_res @ s_{t-1}),  U = X @ W_in^T
// T=16384 steps, R=1024 reservoir, I=128 input. W_res ~5% dense.
//
// R4 changes vs R3 (9.26ms):
//  - 16-CTA cluster (nonportable), 64 rows/CTA, 64 threads, 1 row/thread.
//    No partial reduction / S1 barrier.
//  - Gathers are 2 instr/element: precomputed absolute smem addresses in
//    registers (cols stored as byte offsets at build), LDS [r]/[r+4096]
//    variants selected on t&1.
//  - Distributed remote mbar arrives (tid<16, one peer each).
//  - k_prep: build + gemm fused in one launch (build hides under gemm).

#define T_STEPS 16384
#define R_DIM   1024
#define I_DIM   128
#define NCTA    16
#define CHUNK   64      // rows per CTA
#define ELLCAP  192     // max slots per row (global build clamp)
#define KREG    40      // pairs held in registers per thread
#define SREM    24      // extra pairs staged in smem (KREG+SREM = 64 = clamp)

__device__ float    d_U[(size_t)T_STEPS * R_DIM];        // 64 MiB
__device__ float2   d_ellv2[(ELLCAP / 2) * R_DIM];       // pair-packed vals
__device__ unsigned d_ellc2[(ELLCAP / 2) * R_DIM];       // pair-packed BYTE offsets (2xu16)
__device__ int      d_kgrp[R_DIM / 32];                  // slots per 32-row group (even)

__device__ __forceinline__ uint32_t smaddr(const void* p) {
    uint32_t a;
    asm("{ .reg .u64 t; cvta.to.shared.u64 t, %1; cvt.u32.u64 %0, t; }"
        : "=r"(a) : "l"(p));
    return a;
}

// ---------------------------------------------------------------------------
// Fused prep kernel: blocks [0,32) build the bank-conflict-free ELL schedule
// (one warp per 32-row group); blocks [32, 32+4096) compute U = X @ W_in^T.
// Build hides under the GEMM in a single launch.
#define B2_BCOL 0
#define B2_BVAL (32 * 32 * 16 * 2)
#define B2_BCNT (B2_BVAL + 32 * 32 * 16 * 4)
#define B2_MASK (B2_BCNT + 32 * 32 * 4)
#define B2_SMEM (B2_MASK + 32 * 4)
#define GEMM_TILES_T (T_STEPS / 64)
#define GEMM_TILES_R (R_DIM / 64)
#define PREP_BLOCKS (32 + GEMM_TILES_T * GEMM_TILES_R)

__global__ __launch_bounds__(256) void k_prep(const float* __restrict__ W,
                                              const float* __restrict__ X,
                                              const float* __restrict__ Win) {
    if (blockIdx.x < 32) {
        // ---------------- build path (threads 0..31 of build blocks) -------
        if (threadIdx.x >= 32) return;
        extern __shared__ unsigned char sm[];
        unsigned short* bcol    = (unsigned short*)(sm + B2_BCOL);  // [r][b][16]
        float*          bval    = (float*)(sm + B2_BVAL);           // [r][b][16]
        int*            bcnt    = (int*)(sm + B2_BCNT);             // [r][b]
        unsigned*       rowmask = (unsigned*)(sm + B2_MASK);        // [r]

        int g = blockIdx.x;
        int r = threadIdx.x;  // 0..31

        for (int b = 0; b < 32; b++) bcnt[r * 32 + b] = 0;
        const float4* Wr4 = (const float4*)(W + (size_t)(g * 32 + r) * R_DIM);
        for (int c4 = 0; c4 < R_DIM / 4; c4++) {
            float4 w4 = Wr4[c4];
            float wv[4] = {w4.x, w4.y, w4.z, w4.w};
#pragma unroll
            for (int j = 0; j < 4; j++) {
                float w = wv[j];
                if (w != 0.0f) {
                    int c = c4 * 4 + j;
                    int b = c & 31;
                    int i = bcnt[r * 32 + b]++;
                    if (i < 16) {
                        bcol[(r * 32 + b) * 16 + i] = (unsigned short)c;
                        bval[(r * 32 + b) * 16 + i] = w;
                    }
                }
            }
        }
        unsigned m = 0;
        for (int b = 0; b < 32; b++)
            if (bcnt[r * 32 + b] > 0) m |= 1u << b;
        rowmask[r] = m;
        __syncwarp();

        if (r == 0) {
            int rows_left = 0;
            for (int i = 0; i < 32; i++)
                if (rowmask[i]) rows_left++;
            int s = 0;
            while (rows_left > 0 && s < ELLCAP) {
                unsigned used = 0, pickedmask = 0;
                for (int i = 0; i < 32; i++) {
                    int rr = (s + i) & 31;
                    unsigned avail = rowmask[rr] & ~used;
                    if (avail) {
                        int b = __ffs(avail) - 1;
                        int c = --bcnt[rr * 32 + b];
                        unsigned short col = bcol[(rr * 32 + b) * 16 + c];
                        float v = bval[(rr * 32 + b) * 16 + c];
                        if (c == 0) {
                            rowmask[rr] &= ~(1u << b);
                            if (!rowmask[rr]) rows_left--;
                        }
                        used |= 1u << b;
                        pickedmask |= 1u << rr;
                        size_t idx = (size_t)(s >> 1) * R_DIM + g * 32 + rr;
                        ((float*)d_ellv2)[idx * 2 + (s & 1)] = v;
                        // store BYTE offset (col*4) for addr-precompute in k_esn
                        ((unsigned short*)d_ellc2)[idx * 2 + (s & 1)] =
                            (unsigned short)(col * 4);
                    }
                }
                unsigned freeb = ~used;
                for (int rr = 0; rr < 32; rr++) {
                    if (!((pickedmask >> rr) & 1)) {
                        int b = __ffs(freeb) - 1;
                        freeb &= freeb - 1;
                        size_t idx = (size_t)(s >> 1) * R_DIM + g * 32 + rr;
                        ((float*)d_ellv2)[idx * 2 + (s & 1)] = 0.0f;
                        ((unsigned short*)d_ellc2)[idx * 2 + (s & 1)] =
                            (unsigned short)(b * 4);
                    }
                }
                s++;
            }
            if (s & 1) {  // pad to even slot count; pads bank-distinct
                for (int rr = 0; rr < 32; rr++) {
                    size_t idx = (size_t)(s >> 1) * R_DIM + g * 32 + rr;
                    ((float*)d_ellv2)[idx * 2 + 1] = 0.0f;
                    ((unsigned short*)d_ellc2)[idx * 2 + 1] = (unsigned short)(rr * 4);
                }
                s++;
            }
            d_kgrp[g] = s;
        }
        return;
    }

    // ---------------- gemm path: U = X @ W_in^T, 64x64 tiles ---------------
    __shared__ float xs[64][68];
    __shared__ float ws[64][68];
    int gb = blockIdx.x - 32;
    int bt = (gb % GEMM_TILES_T) * 64;
    int br = (gb / GEMM_TILES_T) * 64;
    int ty = threadIdx.x >> 4;
    int tx = threadIdx.x & 15;

    float acc[4][4];
#pragma unroll
    for (int i = 0; i < 4; i++)
#pragma unroll
        for (int j = 0; j < 4; j++) acc[i][j] = 0.0f;

    for (int kc = 0; kc < I_DIM; kc += 64) {
        for (int i = threadIdx.x; i < 64 * 16; i += 256) {
            int rr = i >> 4, cc = i & 15;
            *(float4*)&xs[rr][cc * 4] = *(const float4*)&X[(size_t)(bt + rr) * I_DIM + kc + cc * 4];
            *(float4*)&ws[rr][cc * 4] = *(const float4*)&Win[(size_t)(br + rr) * I_DIM + kc + cc * 4];
        }
        __syncthreads();
#pragma unroll
        for (int k = 0; k < 64; k++) {
            float a[4], b[4];
#pragma unroll
            for (int i = 0; i < 4; i++) a[i] = xs[ty + 16 * i][k];
#pragma unroll
            for (int j = 0; j < 4; j++) b[j] = ws[tx + 16 * j][k];
#pragma unroll
            for (int i = 0; i < 4; i++)
#pragma unroll
                for (int j = 0; j < 4; j++) acc[i][j] += a[i] * b[j];
        }
        __syncthreads();
    }
#pragma unroll
    for (int i = 0; i < 4; i++)
#pragma unroll
        for (int j = 0; j < 4; j++)
            d_U[(size_t)(bt + ty + 16 * i) * R_DIM + br + tx + 16 * j] = acc[i][j];
}

// ---------------------------------------------------------------------------
// Recurrence kernel: 16-CTA cluster, 64 threads, one reservoir row per thread.
__global__ __launch_bounds__(64, 1)
void k_esn(const float* __restrict__ state0, float* __restrict__ out) {
    __shared__ float    sbuf[2 * R_DIM];          // double-buffered full state
    __shared__ float2   srv[SREM][CHUNK];         // remainder pairs (vals)
    __shared__ unsigned src_[SREM][CHUNK];        // remainder pairs (byte-off pairs)
    __shared__ unsigned long long mbar[2];
    __shared__ int kg_s[2];

    int tid = threadIdx.x;          // 0..63
    int cta = blockIdx.x;           // == cluster rank (1-D single-cluster grid)
    int grow = cta * CHUNK + tid;   // global row owned by this thread

    uint32_t sb_a = smaddr(sbuf);
    uint32_t mb_a = smaddr(mbar);

    if (tid < 2) {
        int v = d_kgrp[cta * 2 + tid];
        kg_s[tid] = (v > 2 * (KREG + SREM)) ? 2 * (KREG + SREM) : v;
    }
    if (tid == 0) {
        asm volatile("mbarrier.init.shared.b64 [%0], %1;" :: "r"(mb_a), "r"(NCTA));
        asm volatile("mbarrier.init.shared.b64 [%0], %1;" :: "r"(mb_a + 8), "r"(NCTA));
    }
    for (int i = tid; i < R_DIM; i += CHUNK) sbuf[i] = state0[i];
    __syncthreads();

    // stage remainder pairs [KREG, Kp) into smem
    for (int idx = tid; idx < SREM * CHUNK; idx += CHUNK) {
        int p = KREG + idx / CHUNK, lr = idx % CHUNK;
        int kp2 = kg_s[lr >> 5] >> 1;
        if (p < kp2) {
            srv[p - KREG][lr] = d_ellv2[(size_t)p * R_DIM + cta * CHUNK + lr];
            src_[p - KREG][lr] = d_ellc2[(size_t)p * R_DIM + cta * CHUNK + lr];
        }
    }
    __syncthreads();

    // all CTAs' mbarrier.init complete before use
    asm volatile("barrier.cluster.arrive.aligned;" ::: "memory");
    asm volatile("barrier.cluster.wait.aligned;" ::: "memory");

    int Kp = kg_s[tid >> 5] >> 1;   // pair count for my row's group

    // ---- preload: values + ABSOLUTE smem addresses into registers --------
    float    va[2 * KREG];
    uint32_t ad[2 * KREG];
    uint32_t pada = sb_a + (uint32_t)((tid & 31) * 4);  // lane-distinct pad bank
#pragma unroll
    for (int p = 0; p < KREG; p++) {
        if (p < Kp) {
            float2 v = d_ellv2[(size_t)p * R_DIM + grow];
            unsigned c = d_ellc2[(size_t)p * R_DIM + grow];
            va[2 * p] = v.x;     ad[2 * p] = sb_a + (c & 0xFFFFu);
            va[2 * p + 1] = v.y; ad[2 * p + 1] = sb_a + (c >> 16);
        } else {
            va[2 * p] = 0.0f;     ad[2 * p] = pada;
            va[2 * p + 1] = 0.0f; ad[2 * p + 1] = pada;
        }
    }

    float u = __ldg(&d_U[grow]);  // prefetch U for t=0

    for (int t = 0; t < T_STEPS; t++) {
        float acc = 0.0f;
        if (!(t & 1)) {
#pragma unroll
            for (int e = 0; e < 2 * KREG; e++) {
                float x;
                asm volatile("ld.shared.f32 %0, [%1];" : "=f"(x) : "r"(ad[e]));
                acc += va[e] * x;
            }
        } else {
#pragma unroll
            for (int e = 0; e < 2 * KREG; e++) {
                float x;
                asm volatile("ld.shared.f32 %0, [%1+4096];" : "=f"(x) : "r"(ad[e]));
                acc += va[e] * x;
            }
        }
        // rare remainder pairs from smem stage
        for (int p = KREG; p < Kp; p++) {
            float2 v = srv[p - KREG][tid];
            unsigned c = src_[p - KREG][tid];
            const float* s_rd = sbuf + (t & 1) * R_DIM;
            acc += v.x * s_rd[(c & 0xFFFFu) >> 2];
            acc += v.y * s_rd[(c >> 16) >> 2];
        }

        float y = u + acc;
        // tanh(y) = 1 - 2/(exp(2y)+1); exact identity, approx exp/div
        float e2 = __expf(2.0f * y);
        float s = 1.0f - __fdividef(2.0f, e2 + 1.0f);
        out[(size_t)t * R_DIM + grow] = s;

        // broadcast my new value into every CTA's write buffer via DSMEM
        uint32_t la = sb_a + (uint32_t)((((t & 1) ^ 1) << 12) + grow * 4);
#pragma unroll
        for (int p = 0; p < NCTA; p++) {
            uint32_t ra;
            asm("mapa.shared::cluster.u32 %0, %1, %2;" : "=r"(ra) : "r"(la), "r"(p));
            asm volatile("st.shared::cluster.f32 [%0], %1;" :: "r"(ra), "f"(s));
        }
        int tn = (t + 1 < T_STEPS) ? (t + 1) : t;
        u = __ldg(&d_U[(size_t)tn * R_DIM + grow]);  // prefetch next U

        __syncthreads();  // all this CTA's stores + state reads done

        uint32_t mba = mb_a + (uint32_t)((t & 1) * 8);
        if (tid < NCTA) {
            // distributed release-arrive: thread p signals peer p's mbar
            uint32_t ra;
            asm("mapa.shared::cluster.u32 %0, %1, %2;" : "=r"(ra) : "r"(mba), "r"(tid));
            asm volatile("mbarrier.arrive.shared::cluster.b64 _, [%0];" :: "r"(ra) : "memory");
        }
        unsigned parity = (t >> 1) & 1;  // each mbar flips every 2 steps
        asm volatile(
            "{ .reg .pred P;\n"
            "W%=:\n"
            " mbarrier.try_wait.parity.acquire.cluster.shared::cta.b64 P, [%0], %1, 0x989680;\n"
            " @!P bra W%=;\n"
            "}" :: "r"(mba), "r"(parity) : "memory");
    }
}

// ---------------------------------------------------------------------------
extern "C" void kernel_launch(void* const* d_in, const int* in_sizes, int n_in,
                              void* d_out, int out_size) {
    const float* X    = (const float*)d_in[0];  // (T, I)
    const float* Win  = (const float*)d_in[1];  // (R, I)
    const float* Wres = (const float*)d_in[2];  // (R, R)
    const float* s0   = (const float*)d_in[3];  // (R,)
    float* out = (float*)d_out;                 // (T, R)

    cudaFuncSetAttribute(k_prep, cudaFuncAttributeMaxDynamicSharedMemorySize, B2_SMEM);
    cudaFuncSetAttribute(k_esn, cudaFuncAttributeNonPortableClusterSizeAllowed, 1);

    k_prep<<<PREP_BLOCKS, 256, B2_SMEM>>>(Wres, X, Win);

    cudaLaunchConfig_t cfg = {};
    cfg.gridDim = {NCTA, 1, 1};
    cfg.blockDim = {64, 1, 1};
    cfg.dynamicSmemBytes = 0;
    cudaLaunchAttribute attrs[1];
    attrs[0].id = cudaLaunchAttributeClusterDimension;
    attrs[0].val.clusterDim = {NCTA, 1, 1};
    cfg.attrs = attrs;
    cfg.numAttrs = 1;
    cudaLaunchKernelEx(&cfg, k_esn, (const float*)s0, (float*)out);
}